// round 11
// baseline (speedup 1.0000x reference)
#include <cuda_runtime.h>
#include <cuda_fp16.h>
#include <cstdint>
#include <math.h>

// B=8, S=4096, D=1024, H=8, SEG=4, head_dim=128.
// Padding dead; segment shuffle is a permutation -> segments = consecutive
// 4-token groups. Weights fused: WF = in_proj @ (Wqk|Wqk|Wv), CF = in_proj@b + b.
// All GEMMs single-pass fp16 mma.sync, fp32 accum (measured rel_err 5.49e-4).
// R11: R10 falsified the occupancy theory (2x warps, flat tensor%). Limiter is
// per-MMA smem/L2 traffic + per-CTA overheads. This round: WIDE shape for the
// big GEMMs -- CTA 128x256, 512 thr, warp 32x64 (same 16 warps/SM as R9) -->
// less write/L2 traffic, half the CTAs. Fusion keeps R9's 128x128 2-CTA shape.
// Prep (convert+transpose+bias) merged into one kernel.

#define DMODEL 1024
#define NTOK   32768
#define NQKV   3072

#define HSTAGE 4
#define ROWB   80u
#define A_ROWS 128u

// narrow: BN=128, 256 thr, 2 CTAs/SM
#define N_STAGE_BYTES ((A_ROWS + 128u) * ROWB)      // 20480
#define N_SMEM_TOTAL (HSTAGE * N_STAGE_BYTES)       // 81920
// wide: BN=256, 512 thr, 1 CTA/SM
#define W_STAGE_BYTES ((A_ROWS + 256u) * ROWB)      // 30720
#define W_SMEM_TOTAL (HSTAGE * W_STAGE_BYTES)       // 122880

// ------------------------- device scratch (no allocs) -----------------------
__device__ __align__(256) float   g_CF[NQKV];
__device__ __align__(256) __half  g_QKV16[(size_t)NTOK * NQKV];
__device__ __align__(256) __half  g_x16[(size_t)NTOK * DMODEL];
__device__ __align__(256) __half  g_WF16[(size_t)NQKV * DMODEL];
__device__ __align__(256) __half  g_O16[(size_t)NTOK * DMODEL];
__device__ __align__(256) __half  g_ow16[(size_t)DMODEL * DMODEL];
__device__ __align__(256) __half  g_iw16[(size_t)NQKV * DMODEL];
__device__ __align__(256) __half  g_qkT16[(size_t)DMODEL * DMODEL];
__device__ __align__(256) __half  g_vT16[(size_t)DMODEL * DMODEL];

// ------------------------------ helpers -------------------------------------
__device__ __forceinline__ uint32_t smem_u32(const void* p) {
    uint32_t a;
    asm("{ .reg .u64 t; cvta.to.shared.u64 t, %1; cvt.u32.u64 %0, t; }" : "=r"(a) : "l"(p));
    return a;
}
__device__ __forceinline__ void cp16(uint32_t dst, const void* src) {
    asm volatile("cp.async.cg.shared.global [%0], [%1], 16;" :: "r"(dst), "l"(src) : "memory");
}
#define CP_COMMIT() asm volatile("cp.async.commit_group;" ::: "memory")
#define CP_WAIT2()  asm volatile("cp.async.wait_group 2;" ::: "memory")

#define LDSM_X4(R, a) \
    asm volatile("ldmatrix.sync.aligned.m8n8.x4.shared.b16 {%0,%1,%2,%3}, [%4];" \
        : "=r"((R)[0]), "=r"((R)[1]), "=r"((R)[2]), "=r"((R)[3]) : "r"(a))

#define MMA_FP16(d, a, b0, b1) \
    asm volatile("mma.sync.aligned.m16n8k16.row.col.f32.f16.f16.f32 " \
        "{%0,%1,%2,%3}, {%4,%5,%6,%7}, {%8,%9}, {%0,%1,%2,%3};" \
        : "+f"((d)[0]), "+f"((d)[1]), "+f"((d)[2]), "+f"((d)[3]) \
        : "r"((a)[0]), "r"((a)[1]), "r"((a)[2]), "r"((a)[3]), "r"(b0), "r"(b1))

// ----------------------------------------------------------------------------
// Single-pass fp16 GEMM: C[M,Ntot] = A@B^T (+bias).
// A: [M,K] fp16 K-major; B: [Ntot,K] fp16 K-major.
// B2 != null: row blocks with m0 >= b2row use B2 (fusion merge).
// WIDE=1: CTA 128x256, 512 thr (16 warps 4Mx4N, warp 32x64), 1 CTA/SM.
// WIDE=0: CTA 128x128, 256 thr (8 warps 4Mx2N, warp 32x64), 2 CTAs/SM.
// OUT16=true -> fp16 C16; false -> fp32 C.  4-stage cp.async pipeline.
// ----------------------------------------------------------------------------
template <bool WIDE, bool OUT16>
__global__ void __launch_bounds__(WIDE ? 512 : 256, WIDE ? 1 : 2)
gemm_fp16(const __half* __restrict__ A,
          const __half* __restrict__ B, const __half* __restrict__ B2, int b2row,
          const float* __restrict__ bias, float* __restrict__ C,
          __half* __restrict__ C16, int Ntot, int K)
{
    constexpr int NTHR = WIDE ? 512 : 256;
    constexpr int BN = WIDE ? 256 : 128;
    constexpr uint32_t STG = WIDE ? W_STAGE_BYTES : N_STAGE_BYTES;
    constexpr int CHUNKS = (A_ROWS + BN) * 4;       // 16B chunks per stage
    constexpr int PER_THR = CHUNKS / NTHR;          // 3 (wide) / 4 (narrow)

    extern __shared__ char smem[];
    const uint32_t sb = smem_u32(smem);
    const int tid = threadIdx.x, wid = tid >> 5, lane = tid & 31;
    const int m0 = blockIdx.y * 128, n0 = blockIdx.x * BN;
    const int KT = K >> 5;
    const __half* Bp = (B2 != nullptr && m0 >= b2row) ? B2 : B;

    const int wm = (wid & 3) * 32;       // 4 warps in M
    const int wn = (wid >> 2) * 64;      // 2 (narrow) or 4 (wide) warps in N
    const int g = lane >> 3, r = lane & 7;

    const uint32_t aRow = (uint32_t)(wm + (g & 1) * 8 + r);
    const uint32_t aCk  = (uint32_t)(g >> 1);
    const uint32_t bRow = (uint32_t)(wn + (g >> 1) * 8 + r);
    const uint32_t bCk  = (uint32_t)(g & 1);

    float acc[2][8][4];
#pragma unroll
    for (int i = 0; i < 2; i++)
#pragma unroll
        for (int j = 0; j < 8; j++)
#pragma unroll
            for (int q = 0; q < 4; q++) acc[i][j][q] = 0.0f;

    auto load_tile = [&](int kt, int s) {
        const int k0 = kt << 5;
        const uint32_t sbase = sb + (uint32_t)s * STG;
#pragma unroll
        for (int q = 0; q < PER_THR; q++) {
            int c = tid + q * NTHR;
            const __half* src;
            uint32_t dst;
            if (c < 512) {                        // A: 128 rows x 4 chunks
                int rr = c >> 2, ck = c & 3;
                src = A + (size_t)(m0 + rr) * K + k0 + ck * 8;
                dst = sbase + (uint32_t)rr * ROWB + (uint32_t)ck * 16u;
            } else {                              // B: BN rows x 4 chunks
                int cc = c - 512;
                int rr = cc >> 2, ck = cc & 3;
                src = Bp + (size_t)(n0 + rr) * K + k0 + ck * 8;
                dst = sbase + A_ROWS * ROWB + (uint32_t)rr * ROWB + (uint32_t)ck * 16u;
            }
            cp16(dst, src);
        }
    };

    load_tile(0, 0); CP_COMMIT();
    load_tile(1, 1); CP_COMMIT();
    load_tile(2, 2); CP_COMMIT();

    for (int kt = 0; kt < KT; kt++) {
        CP_WAIT2();
        __syncthreads();
        if (kt + 3 < KT) load_tile(kt + 3, (kt + 3) % HSTAGE);
        CP_COMMIT();

        const uint32_t sbase = sb + (uint32_t)(kt % HSTAGE) * STG;
#pragma unroll
        for (int kc = 0; kc < 2; kc++) {
            uint32_t af[2][4], bf[4][4];
            const uint32_t kofs = (uint32_t)(kc * 2) * 16u;
#pragma unroll
            for (int mi = 0; mi < 2; mi++)
                LDSM_X4(af[mi], sbase + (aRow + mi * 16) * ROWB + kofs + aCk * 16u);
#pragma unroll
            for (int bj = 0; bj < 4; bj++)
                LDSM_X4(bf[bj], sbase + A_ROWS * ROWB + (bRow + bj * 16) * ROWB + kofs + bCk * 16u);
#pragma unroll
            for (int mi = 0; mi < 2; mi++)
#pragma unroll
                for (int nj = 0; nj < 8; nj++)
                    MMA_FP16(acc[mi][nj], af[mi],
                             bf[nj >> 1][(nj & 1) * 2], bf[nj >> 1][(nj & 1) * 2 + 1]);
        }
    }

    const int rb = lane >> 2, cb = (lane & 3) * 2;
#pragma unroll
    for (int mi = 0; mi < 2; mi++) {
#pragma unroll
        for (int nj = 0; nj < 8; nj++) {
            int row0 = m0 + wm + mi * 16 + rb;
            int col = n0 + wn + nj * 8 + cb;
            float b0 = bias ? bias[col] : 0.0f;
            float b1 = bias ? bias[col + 1] : 0.0f;
            float v0 = acc[mi][nj][0] + b0, v1 = acc[mi][nj][1] + b1;
            float v2 = acc[mi][nj][2] + b0, v3 = acc[mi][nj][3] + b1;
            if (OUT16) {
                *(__half2*)(C16 + (size_t)row0 * Ntot + col) =
                    __halves2half2(__float2half_rn(v0), __float2half_rn(v1));
                *(__half2*)(C16 + (size_t)(row0 + 8) * Ntot + col) =
                    __halves2half2(__float2half_rn(v2), __float2half_rn(v3));
            } else {
                *(float2*)(C + (size_t)row0 * Ntot + col) = make_float2(v0, v1);
                *(float2*)(C + (size_t)(row0 + 8) * Ntot + col) = make_float2(v2, v3);
            }
        }
    }
}

// ---------------- merged prep: converts + transposes + fused bias ------------
#define N4_X  (NTOK * DMODEL / 4)            // 8388608
#define N4_IW (NQKV * DMODEL / 4)            // 786432
#define N4_OW (DMODEL * DMODEL / 4)          // 262144
#define N4_ALL (N4_X + N4_IW + N4_OW)        // 9437184
#define CONV_BLOCKS (N4_ALL / 256)           // 36864 (exact)
#define TRANS_BLOCKS 2048                    // 32*32*2
#define BIAS_BLOCKS 384
#define PREP_BLOCKS (CONV_BLOCKS + TRANS_BLOCKS + BIAS_BLOCKS)

__global__ void prep_kernel(const float* __restrict__ x,
                            const float* __restrict__ iw,
                            const float* __restrict__ ow,
                            const float* __restrict__ qk_w,
                            const float* __restrict__ v_w,
                            const float* __restrict__ in_b,
                            const float* __restrict__ bqk,
                            const float* __restrict__ bv)
{
    __shared__ float t[32][33];
    const int b = blockIdx.x, tid = threadIdx.x;

    if (b < CONV_BLOCKS) {
        // fp32 -> fp16 converts: x | in_w | out_w
        int j = b * 256 + tid;
        const float* in;
        __half* out;
        if (j < N4_X) { in = x; out = g_x16; }
        else if (j < N4_X + N4_IW) { j -= N4_X; in = iw; out = g_iw16; }
        else { j -= N4_X + N4_IW; in = ow; out = g_ow16; }
        float4 v = ((const float4*)in)[j];
        ((__half2*)out)[2 * j + 0] = __halves2half2(__float2half_rn(v.x), __float2half_rn(v.y));
        ((__half2*)out)[2 * j + 1] = __halves2half2(__float2half_rn(v.z), __float2half_rn(v.w));
    } else if (b < CONV_BLOCKS + TRANS_BLOCKS) {
        // transpose 1024x1024 fp32 -> fp16 (qk_w, v_w)
        int bb = b - CONV_BLOCKS;
        int z = bb >> 10, rem = bb & 1023;
        const float* W = z ? v_w : qk_w;
        __half* T = z ? g_vT16 : g_qkT16;
        int bx = (rem & 31) * 32, by = (rem >> 5) * 32;
        int tx = tid & 31, ty = tid >> 5;     // 32 x 8
        for (int j = ty; j < 32; j += 8)
            t[j][tx] = W[(size_t)(by + j) * DMODEL + bx + tx];
        __syncthreads();
        for (int j = ty; j < 32; j += 8)
            T[(size_t)(bx + j) * DMODEL + by + tx] = __float2half_rn(t[tx][j]);
    } else {
        // fused bias: CF = in_w @ (bqk|bv) + in_b
        int bb = b - CONV_BLOCKS - TRANS_BLOCKS;
        int gw = (bb * 256 + tid) >> 5;
        int lane = tid & 31;
        if (gw < NQKV) {
            const float* bvec = (gw < 2048) ? bqk : bv;
            const float* Arow = iw + (size_t)gw * DMODEL;
            float s = 0.0f;
            for (int j = lane; j < DMODEL; j += 32) s += Arow[j] * bvec[j];
#pragma unroll
            for (int off = 16; off; off >>= 1) s += __shfl_xor_sync(0xffffffffu, s, off);
            if (lane == 0) g_CF[gw] = s + in_b[gw];
        }
    }
}

// -------- segment attention (SEG=4, per head), fp16 in / fp16 out ------------
__global__ void attn_kernel()
{
    int gw   = (int)((blockIdx.x * blockDim.x + threadIdx.x) >> 5);
    int lane = threadIdx.x & 31;
    if (gw >= (NTOK / 4) * 8) return;
    int seg = gw >> 3, h = gw & 7, t0 = seg << 2;

    const __half* base = g_QKV16 + (size_t)t0 * NQKV + h * 128 + lane * 4;
    float4 q[4], k[4], v[4];
#pragma unroll
    for (int i = 0; i < 4; i++) {
        const __half2* qp = (const __half2*)(base + (size_t)i * NQKV);
        const __half2* kp = (const __half2*)(base + (size_t)i * NQKV + 1024);
        const __half2* vp = (const __half2*)(base + (size_t)i * NQKV + 2048);
        float2 q0 = __half22float2(qp[0]), q1 = __half22float2(qp[1]);
        float2 k0 = __half22float2(kp[0]), k1 = __half22float2(kp[1]);
        float2 v0 = __half22float2(vp[0]), v1 = __half22float2(vp[1]);
        q[i] = make_float4(q0.x, q0.y, q1.x, q1.y);
        k[i] = make_float4(k0.x, k0.y, k1.x, k1.y);
        v[i] = make_float4(v0.x, v0.y, v1.x, v1.y);
    }
    float s[4][4];
#pragma unroll
    for (int i = 0; i < 4; i++)
#pragma unroll
        for (int j = 0; j < 4; j++)
            s[i][j] = q[i].x * k[j].x + q[i].y * k[j].y + q[i].z * k[j].z + q[i].w * k[j].w;
#pragma unroll
    for (int off = 16; off; off >>= 1)
#pragma unroll
        for (int i = 0; i < 4; i++)
#pragma unroll
            for (int j = 0; j < 4; j++)
                s[i][j] += __shfl_xor_sync(0xffffffffu, s[i][j], off);

    const float scale = 0.08838834764831845f;
    float p[4][4];
#pragma unroll
    for (int i = 0; i < 4; i++) {
        float m = -1e30f;
#pragma unroll
        for (int j = 0; j < 4; j++) {
            float sv = (j == i) ? -1e30f : s[i][j] * scale;
            p[i][j] = sv; m = fmaxf(m, sv);
        }
        float sum = 0.0f;
#pragma unroll
        for (int j = 0; j < 4; j++) { p[i][j] = expf(p[i][j] - m); sum += p[i][j]; }
        float inv = 1.0f / sum;
#pragma unroll
        for (int j = 0; j < 4; j++) p[i][j] *= inv;
    }
    __half* ob = g_O16 + (size_t)t0 * DMODEL + h * 128 + lane * 4;
#pragma unroll
    for (int i = 0; i < 4; i++) {
        float o0 = p[i][0]*v[0].x + p[i][1]*v[1].x + p[i][2]*v[2].x + p[i][3]*v[3].x;
        float o1 = p[i][0]*v[0].y + p[i][1]*v[1].y + p[i][2]*v[2].y + p[i][3]*v[3].y;
        float o2 = p[i][0]*v[0].z + p[i][1]*v[1].z + p[i][2]*v[2].z + p[i][3]*v[3].z;
        float o3 = p[i][0]*v[0].w + p[i][1]*v[1].w + p[i][2]*v[2].w + p[i][3]*v[3].w;
        __half2* op = (__half2*)(ob + (size_t)i * DMODEL);
        op[0] = __halves2half2(__float2half_rn(o0), __float2half_rn(o1));
        op[1] = __halves2half2(__float2half_rn(o2), __float2half_rn(o3));
    }
}

// ----------------------------------------------------------------------------
extern "C" void kernel_launch(void* const* d_in, const int* in_sizes, int n_in,
                              void* d_out, int out_size)
{
    const float* x     = (const float*)d_in[0];
    const float* qk_w  = (const float*)d_in[1];
    const float* qk_b  = (const float*)d_in[2];
    const float* v_w   = (const float*)d_in[3];
    const float* v_b   = (const float*)d_in[4];
    const float* in_w  = (const float*)d_in[5];
    const float* in_b  = (const float*)d_in[6];
    const float* out_w = (const float*)d_in[7];
    const float* out_b = (const float*)d_in[8];
    float* out = (float*)d_out;
    (void)in_sizes; (void)n_in; (void)out_size;

    float *CF;
    __half *QKV16, *x16, *WF16, *O16, *ow16, *iw16, *qkT16, *vT16;
    cudaGetSymbolAddress((void**)&CF, g_CF);
    cudaGetSymbolAddress((void**)&QKV16, g_QKV16);
    cudaGetSymbolAddress((void**)&x16, g_x16);
    cudaGetSymbolAddress((void**)&WF16, g_WF16);
    cudaGetSymbolAddress((void**)&O16, g_O16);
    cudaGetSymbolAddress((void**)&ow16, g_ow16);
    cudaGetSymbolAddress((void**)&iw16, g_iw16);
    cudaGetSymbolAddress((void**)&qkT16, g_qkT16);
    cudaGetSymbolAddress((void**)&vT16, g_vT16);

    static bool attr_set = false;
    if (!attr_set) {
        cudaFuncSetAttribute((const void*)gemm_fp16<false, true>,
                             cudaFuncAttributeMaxDynamicSharedMemorySize, N_SMEM_TOTAL);
        cudaFuncSetAttribute((const void*)gemm_fp16<true, true>,
                             cudaFuncAttributeMaxDynamicSharedMemorySize, W_SMEM_TOTAL);
        cudaFuncSetAttribute((const void*)gemm_fp16<true, false>,
                             cudaFuncAttributeMaxDynamicSharedMemorySize, W_SMEM_TOTAL);
        attr_set = true;
    }

    // 0) merged prep: converts + transposes + fused bias
    prep_kernel<<<PREP_BLOCKS, 256>>>(x, in_w, out_w, qk_w, v_w, in_b, qk_b, v_b);
    // 1) weight fusion (narrow shape; rows >= 2048 use vT16)
    gemm_fp16<false, true><<<dim3(DMODEL / 128, NQKV / 128), 256, N_SMEM_TOTAL>>>(
        iw16, qkT16, vT16, 2048, nullptr, nullptr, WF16, DMODEL, DMODEL);
    // 2) QKV = X @ WF^T + CF  [32768, 3072], wide shape, fp16 in/out
    gemm_fp16<true, true><<<dim3(NQKV / 256, NTOK / 128), 512, W_SMEM_TOTAL>>>(
        x16, WF16, nullptr, 0, CF, nullptr, QKV16, NQKV, DMODEL);
    // 3) segment attention (fp16 -> fp16)
    attn_kernel<<<16384, 128>>>();
    // 4) out = O @ out_w^T + out_b  [32768, 1024], wide shape, fp16 -> fp32
    gemm_fp16<true, false><<<dim3(DMODEL / 256, NTOK / 128), 512, W_SMEM_TOTAL>>>(
        O16, ow16, nullptr, 0, out_b, out, nullptr, DMODEL, DMODEL);
}

// round 12
// speedup vs baseline: 1.1386x; 1.1386x over previous
#include <cuda_runtime.h>
#include <cuda_fp16.h>
#include <cstdint>
#include <math.h>

// B=8, S=4096, D=1024, H=8, SEG=4, head_dim=128.
// Padding dead; segment shuffle is a permutation -> segments = consecutive
// 4-token groups. Weights fused: WF = in_proj @ (Wqk|Wqk|Wv), CF = in_proj@b + b.
// All GEMMs single-pass fp16 mma.sync, fp32 accum (measured rel_err 5.49e-4).
// R12: shape scan complete -- R9's config (CTA 128x128, 256 thr, 8 warps
// 4Mx2N warp 32x64, 4 stages, 2 CTAs/SM) is the measured optimum (971.9 vs
// 1000 @ 32 warps, 1099 @ wide). Revert GEMMs to it exactly; keep R11's
// merged prep kernel (same work, fewer launch tails).

#define DMODEL 1024
#define NTOK   32768
#define NQKV   3072

#define HSTAGE 4
#define ROWB   80u
#define A_ROWS 128u
#define B_ROWS 128u
#define H_A_OFF 0u
#define H_B_OFF (A_ROWS * ROWB)                     // 10240
#define H_STAGE_BYTES ((A_ROWS + B_ROWS) * ROWB)    // 20480
#define H_SMEM_TOTAL (HSTAGE * H_STAGE_BYTES)       // 81920 -> 2 CTAs/SM

// ------------------------- device scratch (no allocs) -----------------------
__device__ __align__(256) float   g_CF[NQKV];
__device__ __align__(256) __half  g_QKV16[(size_t)NTOK * NQKV];
__device__ __align__(256) __half  g_x16[(size_t)NTOK * DMODEL];
__device__ __align__(256) __half  g_WF16[(size_t)NQKV * DMODEL];
__device__ __align__(256) __half  g_O16[(size_t)NTOK * DMODEL];
__device__ __align__(256) __half  g_ow16[(size_t)DMODEL * DMODEL];
__device__ __align__(256) __half  g_iw16[(size_t)NQKV * DMODEL];
__device__ __align__(256) __half  g_qkT16[(size_t)DMODEL * DMODEL];
__device__ __align__(256) __half  g_vT16[(size_t)DMODEL * DMODEL];

// ------------------------------ helpers -------------------------------------
__device__ __forceinline__ uint32_t smem_u32(const void* p) {
    uint32_t a;
    asm("{ .reg .u64 t; cvta.to.shared.u64 t, %1; cvt.u32.u64 %0, t; }" : "=r"(a) : "l"(p));
    return a;
}
__device__ __forceinline__ void cp16(uint32_t dst, const void* src) {
    asm volatile("cp.async.cg.shared.global [%0], [%1], 16;" :: "r"(dst), "l"(src) : "memory");
}
#define CP_COMMIT() asm volatile("cp.async.commit_group;" ::: "memory")
#define CP_WAIT2()  asm volatile("cp.async.wait_group 2;" ::: "memory")

#define LDSM_X4(R, a) \
    asm volatile("ldmatrix.sync.aligned.m8n8.x4.shared.b16 {%0,%1,%2,%3}, [%4];" \
        : "=r"((R)[0]), "=r"((R)[1]), "=r"((R)[2]), "=r"((R)[3]) : "r"(a))

#define MMA_FP16(d, a, b0, b1) \
    asm volatile("mma.sync.aligned.m16n8k16.row.col.f32.f16.f16.f32 " \
        "{%0,%1,%2,%3}, {%4,%5,%6,%7}, {%8,%9}, {%0,%1,%2,%3};" \
        : "+f"((d)[0]), "+f"((d)[1]), "+f"((d)[2]), "+f"((d)[3]) \
        : "r"((a)[0]), "r"((a)[1]), "r"((a)[2]), "r"((a)[3]), "r"(b0), "r"(b1))

// ----------------------------------------------------------------------------
// Single-pass fp16 GEMM: C[M,Ntot] = A@B^T (+bias).  [R9 optimum shape]
// A: [M,K] fp16 K-major; B: [Ntot,K] fp16 K-major.
// B2 != null: row blocks with m0 >= b2row use B2 instead of B (fusion merge).
// CTA 128x128, BK=32, 256 threads (8 warps, 4Mx2N, warp 32x64), 4 stages,
// 2 CTAs/SM. OUT16=true -> fp16 C16; false -> fp32 C.
// ----------------------------------------------------------------------------
template <bool OUT16>
__global__ void __launch_bounds__(256, 2)
gemm_fp16(const __half* __restrict__ A,
          const __half* __restrict__ B, const __half* __restrict__ B2, int b2row,
          const float* __restrict__ bias, float* __restrict__ C,
          __half* __restrict__ C16, int Ntot, int K)
{
    extern __shared__ char smem[];
    const uint32_t sb = smem_u32(smem);
    const int tid = threadIdx.x, wid = tid >> 5, lane = tid & 31;
    const int m0 = blockIdx.y * 128, n0 = blockIdx.x * 128;
    const int KT = K >> 5;
    const __half* Bp = (B2 != nullptr && m0 >= b2row) ? B2 : B;

    const int wm = (wid & 3) * 32;       // 4 warps in M
    const int wn = (wid >> 2) * 64;      // 2 warps in N
    const int g = lane >> 3, r = lane & 7;

    const uint32_t aRow = (uint32_t)(wm + (g & 1) * 8 + r);
    const uint32_t aCk  = (uint32_t)(g >> 1);
    const uint32_t bRow = (uint32_t)(wn + (g >> 1) * 8 + r);
    const uint32_t bCk  = (uint32_t)(g & 1);

    float acc[2][8][4];
#pragma unroll
    for (int i = 0; i < 2; i++)
#pragma unroll
        for (int j = 0; j < 8; j++)
#pragma unroll
            for (int q = 0; q < 4; q++) acc[i][j][q] = 0.0f;

    // 1024 16B chunks/stage (A 512, B 512) -> 4 per thread
    auto load_tile = [&](int kt, int s) {
        const int k0 = kt << 5;
        const uint32_t sbase = sb + (uint32_t)s * H_STAGE_BYTES;
#pragma unroll
        for (int q = 0; q < 4; q++) {
            int c = tid + q * 256;
            const __half* src;
            uint32_t dst;
            if (c < 512) {
                int rr = c >> 2, ck = c & 3;
                src = A + (size_t)(m0 + rr) * K + k0 + ck * 8;
                dst = sbase + H_A_OFF + (uint32_t)rr * ROWB + (uint32_t)ck * 16u;
            } else {
                int cc = c - 512;
                int rr = cc >> 2, ck = cc & 3;
                src = Bp + (size_t)(n0 + rr) * K + k0 + ck * 8;
                dst = sbase + H_B_OFF + (uint32_t)rr * ROWB + (uint32_t)ck * 16u;
            }
            cp16(dst, src);
        }
    };

    load_tile(0, 0); CP_COMMIT();
    load_tile(1, 1); CP_COMMIT();
    load_tile(2, 2); CP_COMMIT();

    for (int kt = 0; kt < KT; kt++) {
        CP_WAIT2();
        __syncthreads();
        if (kt + 3 < KT) load_tile(kt + 3, (kt + 3) % HSTAGE);
        CP_COMMIT();

        const uint32_t sbase = sb + (uint32_t)(kt % HSTAGE) * H_STAGE_BYTES;
#pragma unroll
        for (int kc = 0; kc < 2; kc++) {
            uint32_t af[2][4], bf[4][4];
            const uint32_t kofs = (uint32_t)(kc * 2) * 16u;
#pragma unroll
            for (int mi = 0; mi < 2; mi++)
                LDSM_X4(af[mi], sbase + H_A_OFF + (aRow + mi * 16) * ROWB + kofs + aCk * 16u);
#pragma unroll
            for (int bj = 0; bj < 4; bj++)
                LDSM_X4(bf[bj], sbase + H_B_OFF + (bRow + bj * 16) * ROWB + kofs + bCk * 16u);
#pragma unroll
            for (int mi = 0; mi < 2; mi++)
#pragma unroll
                for (int nj = 0; nj < 8; nj++)
                    MMA_FP16(acc[mi][nj], af[mi],
                             bf[nj >> 1][(nj & 1) * 2], bf[nj >> 1][(nj & 1) * 2 + 1]);
        }
    }

    const int rb = lane >> 2, cb = (lane & 3) * 2;
#pragma unroll
    for (int mi = 0; mi < 2; mi++) {
#pragma unroll
        for (int nj = 0; nj < 8; nj++) {
            int row0 = m0 + wm + mi * 16 + rb;
            int col = n0 + wn + nj * 8 + cb;
            float b0 = bias ? bias[col] : 0.0f;
            float b1 = bias ? bias[col + 1] : 0.0f;
            float v0 = acc[mi][nj][0] + b0, v1 = acc[mi][nj][1] + b1;
            float v2 = acc[mi][nj][2] + b0, v3 = acc[mi][nj][3] + b1;
            if (OUT16) {
                *(__half2*)(C16 + (size_t)row0 * Ntot + col) =
                    __halves2half2(__float2half_rn(v0), __float2half_rn(v1));
                *(__half2*)(C16 + (size_t)(row0 + 8) * Ntot + col) =
                    __halves2half2(__float2half_rn(v2), __float2half_rn(v3));
            } else {
                *(float2*)(C + (size_t)row0 * Ntot + col) = make_float2(v0, v1);
                *(float2*)(C + (size_t)(row0 + 8) * Ntot + col) = make_float2(v2, v3);
            }
        }
    }
}

// ---------------- merged prep: converts + transposes + fused bias ------------
#define N4_X  (NTOK * DMODEL / 4)            // 8388608
#define N4_IW (NQKV * DMODEL / 4)            // 786432
#define N4_OW (DMODEL * DMODEL / 4)          // 262144
#define N4_ALL (N4_X + N4_IW + N4_OW)        // 9437184
#define CONV_BLOCKS (N4_ALL / 256)           // 36864 (exact)
#define TRANS_BLOCKS 2048                    // 32*32*2
#define BIAS_BLOCKS 384
#define PREP_BLOCKS (CONV_BLOCKS + TRANS_BLOCKS + BIAS_BLOCKS)

__global__ void prep_kernel(const float* __restrict__ x,
                            const float* __restrict__ iw,
                            const float* __restrict__ ow,
                            const float* __restrict__ qk_w,
                            const float* __restrict__ v_w,
                            const float* __restrict__ in_b,
                            const float* __restrict__ bqk,
                            const float* __restrict__ bv)
{
    __shared__ float t[32][33];
    const int b = blockIdx.x, tid = threadIdx.x;

    if (b < CONV_BLOCKS) {
        // fp32 -> fp16 converts: x | in_w | out_w
        int j = b * 256 + tid;
        const float* in;
        __half* out;
        if (j < N4_X) { in = x; out = g_x16; }
        else if (j < N4_X + N4_IW) { j -= N4_X; in = iw; out = g_iw16; }
        else { j -= N4_X + N4_IW; in = ow; out = g_ow16; }
        float4 v = ((const float4*)in)[j];
        ((__half2*)out)[2 * j + 0] = __halves2half2(__float2half_rn(v.x), __float2half_rn(v.y));
        ((__half2*)out)[2 * j + 1] = __halves2half2(__float2half_rn(v.z), __float2half_rn(v.w));
    } else if (b < CONV_BLOCKS + TRANS_BLOCKS) {
        // transpose 1024x1024 fp32 -> fp16 (qk_w, v_w)
        int bb = b - CONV_BLOCKS;
        int z = bb >> 10, rem = bb & 1023;
        const float* W = z ? v_w : qk_w;
        __half* T = z ? g_vT16 : g_qkT16;
        int bx = (rem & 31) * 32, by = (rem >> 5) * 32;
        int tx = tid & 31, ty = tid >> 5;     // 32 x 8
        for (int j = ty; j < 32; j += 8)
            t[j][tx] = W[(size_t)(by + j) * DMODEL + bx + tx];
        __syncthreads();
        for (int j = ty; j < 32; j += 8)
            T[(size_t)(bx + j) * DMODEL + by + tx] = __float2half_rn(t[tx][j]);
    } else {
        // fused bias: CF = in_w @ (bqk|bv) + in_b
        int bb = b - CONV_BLOCKS - TRANS_BLOCKS;
        int gw = (bb * 256 + tid) >> 5;
        int lane = tid & 31;
        if (gw < NQKV) {
            const float* bvec = (gw < 2048) ? bqk : bv;
            const float* Arow = iw + (size_t)gw * DMODEL;
            float s = 0.0f;
            for (int j = lane; j < DMODEL; j += 32) s += Arow[j] * bvec[j];
#pragma unroll
            for (int off = 16; off; off >>= 1) s += __shfl_xor_sync(0xffffffffu, s, off);
            if (lane == 0) g_CF[gw] = s + in_b[gw];
        }
    }
}

// -------- segment attention (SEG=4, per head), fp16 in / fp16 out ------------
__global__ void attn_kernel()
{
    int gw   = (int)((blockIdx.x * blockDim.x + threadIdx.x) >> 5);
    int lane = threadIdx.x & 31;
    if (gw >= (NTOK / 4) * 8) return;
    int seg = gw >> 3, h = gw & 7, t0 = seg << 2;

    const __half* base = g_QKV16 + (size_t)t0 * NQKV + h * 128 + lane * 4;
    float4 q[4], k[4], v[4];
#pragma unroll
    for (int i = 0; i < 4; i++) {
        const __half2* qp = (const __half2*)(base + (size_t)i * NQKV);
        const __half2* kp = (const __half2*)(base + (size_t)i * NQKV + 1024);
        const __half2* vp = (const __half2*)(base + (size_t)i * NQKV + 2048);
        float2 q0 = __half22float2(qp[0]), q1 = __half22float2(qp[1]);
        float2 k0 = __half22float2(kp[0]), k1 = __half22float2(kp[1]);
        float2 v0 = __half22float2(vp[0]), v1 = __half22float2(vp[1]);
        q[i] = make_float4(q0.x, q0.y, q1.x, q1.y);
        k[i] = make_float4(k0.x, k0.y, k1.x, k1.y);
        v[i] = make_float4(v0.x, v0.y, v1.x, v1.y);
    }
    float s[4][4];
#pragma unroll
    for (int i = 0; i < 4; i++)
#pragma unroll
        for (int j = 0; j < 4; j++)
            s[i][j] = q[i].x * k[j].x + q[i].y * k[j].y + q[i].z * k[j].z + q[i].w * k[j].w;
#pragma unroll
    for (int off = 16; off; off >>= 1)
#pragma unroll
        for (int i = 0; i < 4; i++)
#pragma unroll
            for (int j = 0; j < 4; j++)
                s[i][j] += __shfl_xor_sync(0xffffffffu, s[i][j], off);

    const float scale = 0.08838834764831845f;
    float p[4][4];
#pragma unroll
    for (int i = 0; i < 4; i++) {
        float m = -1e30f;
#pragma unroll
        for (int j = 0; j < 4; j++) {
            float sv = (j == i) ? -1e30f : s[i][j] * scale;
            p[i][j] = sv; m = fmaxf(m, sv);
        }
        float sum = 0.0f;
#pragma unroll
        for (int j = 0; j < 4; j++) { p[i][j] = expf(p[i][j] - m); sum += p[i][j]; }
        float inv = 1.0f / sum;
#pragma unroll
        for (int j = 0; j < 4; j++) p[i][j] *= inv;
    }
    __half* ob = g_O16 + (size_t)t0 * DMODEL + h * 128 + lane * 4;
#pragma unroll
    for (int i = 0; i < 4; i++) {
        float o0 = p[i][0]*v[0].x + p[i][1]*v[1].x + p[i][2]*v[2].x + p[i][3]*v[3].x;
        float o1 = p[i][0]*v[0].y + p[i][1]*v[1].y + p[i][2]*v[2].y + p[i][3]*v[3].y;
        float o2 = p[i][0]*v[0].z + p[i][1]*v[1].z + p[i][2]*v[2].z + p[i][3]*v[3].z;
        float o3 = p[i][0]*v[0].w + p[i][1]*v[1].w + p[i][2]*v[2].w + p[i][3]*v[3].w;
        __half2* op = (__half2*)(ob + (size_t)i * DMODEL);
        op[0] = __halves2half2(__float2half_rn(o0), __float2half_rn(o1));
        op[1] = __halves2half2(__float2half_rn(o2), __float2half_rn(o3));
    }
}

// ----------------------------------------------------------------------------
extern "C" void kernel_launch(void* const* d_in, const int* in_sizes, int n_in,
                              void* d_out, int out_size)
{
    const float* x     = (const float*)d_in[0];
    const float* qk_w  = (const float*)d_in[1];
    const float* qk_b  = (const float*)d_in[2];
    const float* v_w   = (const float*)d_in[3];
    const float* v_b   = (const float*)d_in[4];
    const float* in_w  = (const float*)d_in[5];
    const float* in_b  = (const float*)d_in[6];
    const float* out_w = (const float*)d_in[7];
    const float* out_b = (const float*)d_in[8];
    float* out = (float*)d_out;
    (void)in_sizes; (void)n_in; (void)out_size;

    float *CF;
    __half *QKV16, *x16, *WF16, *O16, *ow16, *iw16, *qkT16, *vT16;
    cudaGetSymbolAddress((void**)&CF, g_CF);
    cudaGetSymbolAddress((void**)&QKV16, g_QKV16);
    cudaGetSymbolAddress((void**)&x16, g_x16);
    cudaGetSymbolAddress((void**)&WF16, g_WF16);
    cudaGetSymbolAddress((void**)&O16, g_O16);
    cudaGetSymbolAddress((void**)&ow16, g_ow16);
    cudaGetSymbolAddress((void**)&iw16, g_iw16);
    cudaGetSymbolAddress((void**)&qkT16, g_qkT16);
    cudaGetSymbolAddress((void**)&vT16, g_vT16);

    static bool attr_set = false;
    if (!attr_set) {
        cudaFuncSetAttribute(gemm_fp16<true>,  cudaFuncAttributeMaxDynamicSharedMemorySize, H_SMEM_TOTAL);
        cudaFuncSetAttribute(gemm_fp16<false>, cudaFuncAttributeMaxDynamicSharedMemorySize, H_SMEM_TOTAL);
        attr_set = true;
    }

    // 0) merged prep: converts + transposes + fused bias
    prep_kernel<<<PREP_BLOCKS, 256>>>(x, in_w, out_w, qk_w, v_w, in_b, qk_b, v_b);
    // 1) weight fusion (rows >= 2048 use vT16)
    gemm_fp16<true><<<dim3(DMODEL / 128, NQKV / 128), 256, H_SMEM_TOTAL>>>(
        iw16, qkT16, vT16, 2048, nullptr, nullptr, WF16, DMODEL, DMODEL);
    // 2) QKV = X @ WF^T + CF  [32768, 3072], fp16 in/out
    gemm_fp16<true><<<dim3(NQKV / 128, NTOK / 128), 256, H_SMEM_TOTAL>>>(
        x16, WF16, nullptr, 0, CF, nullptr, QKV16, NQKV, DMODEL);
    // 3) segment attention (fp16 -> fp16)
    attn_kernel<<<16384, 128>>>();
    // 4) out = O @ out_w^T + out_b  [32768, 1024], fp16 -> fp32
    gemm_fp16<false><<<dim3(DMODEL / 128, NTOK / 128), 256, H_SMEM_TOTAL>>>(
        O16, ow16, nullptr, 0, out_b, out, nullptr, DMODEL, DMODEL);
}

// round 13
// speedup vs baseline: 1.1446x; 1.0052x over previous
#include <cuda_runtime.h>
#include <cuda_fp16.h>
#include <cstdint>
#include <math.h>

// B=8, S=4096, D=1024, H=8, SEG=4, head_dim=128.
// Padding dead; segment shuffle is a permutation -> segments = consecutive
// 4-token groups. Weights fused: WF = in_proj @ (Wqk|Wqk|Wv), CF = in_proj@b + b.
// All GEMMs single-pass fp16 mma.sync, fp32 accum (measured rel_err 5.49e-4).
// R13: GEMM config locked (R9 shape: 128x128, 256thr, warp 32x64, 4 stages,
// 2 CTAs/SM). This round: memory-shape fixes only --
//   - attn loads/stores via 8B uint2 (was 2x4B __half2)
//   - prep conversion 4x float4 per thread (MLP 4, was 1)

#define DMODEL 1024
#define NTOK   32768
#define NQKV   3072

#define HSTAGE 4
#define ROWB   80u
#define A_ROWS 128u
#define B_ROWS 128u
#define H_A_OFF 0u
#define H_B_OFF (A_ROWS * ROWB)                     // 10240
#define H_STAGE_BYTES ((A_ROWS + B_ROWS) * ROWB)    // 20480
#define H_SMEM_TOTAL (HSTAGE * H_STAGE_BYTES)       // 81920 -> 2 CTAs/SM

// ------------------------- device scratch (no allocs) -----------------------
__device__ __align__(256) float   g_CF[NQKV];
__device__ __align__(256) __half  g_QKV16[(size_t)NTOK * NQKV];
__device__ __align__(256) __half  g_x16[(size_t)NTOK * DMODEL];
__device__ __align__(256) __half  g_WF16[(size_t)NQKV * DMODEL];
__device__ __align__(256) __half  g_O16[(size_t)NTOK * DMODEL];
__device__ __align__(256) __half  g_ow16[(size_t)DMODEL * DMODEL];
__device__ __align__(256) __half  g_iw16[(size_t)NQKV * DMODEL];
__device__ __align__(256) __half  g_qkT16[(size_t)DMODEL * DMODEL];
__device__ __align__(256) __half  g_vT16[(size_t)DMODEL * DMODEL];

// ------------------------------ helpers -------------------------------------
__device__ __forceinline__ uint32_t smem_u32(const void* p) {
    uint32_t a;
    asm("{ .reg .u64 t; cvta.to.shared.u64 t, %1; cvt.u32.u64 %0, t; }" : "=r"(a) : "l"(p));
    return a;
}
__device__ __forceinline__ void cp16(uint32_t dst, const void* src) {
    asm volatile("cp.async.cg.shared.global [%0], [%1], 16;" :: "r"(dst), "l"(src) : "memory");
}
#define CP_COMMIT() asm volatile("cp.async.commit_group;" ::: "memory")
#define CP_WAIT2()  asm volatile("cp.async.wait_group 2;" ::: "memory")

#define LDSM_X4(R, a) \
    asm volatile("ldmatrix.sync.aligned.m8n8.x4.shared.b16 {%0,%1,%2,%3}, [%4];" \
        : "=r"((R)[0]), "=r"((R)[1]), "=r"((R)[2]), "=r"((R)[3]) : "r"(a))

#define MMA_FP16(d, a, b0, b1) \
    asm volatile("mma.sync.aligned.m16n8k16.row.col.f32.f16.f16.f32 " \
        "{%0,%1,%2,%3}, {%4,%5,%6,%7}, {%8,%9}, {%0,%1,%2,%3};" \
        : "+f"((d)[0]), "+f"((d)[1]), "+f"((d)[2]), "+f"((d)[3]) \
        : "r"((a)[0]), "r"((a)[1]), "r"((a)[2]), "r"((a)[3]), "r"(b0), "r"(b1))

// ----------------------------------------------------------------------------
// Single-pass fp16 GEMM: C[M,Ntot] = A@B^T (+bias).  [R9 optimum shape]
// A: [M,K] fp16 K-major; B: [Ntot,K] fp16 K-major.
// B2 != null: row blocks with m0 >= b2row use B2 instead of B (fusion merge).
// CTA 128x128, BK=32, 256 threads (8 warps, 4Mx2N, warp 32x64), 4 stages,
// 2 CTAs/SM. OUT16=true -> fp16 C16; false -> fp32 C.
// ----------------------------------------------------------------------------
template <bool OUT16>
__global__ void __launch_bounds__(256, 2)
gemm_fp16(const __half* __restrict__ A,
          const __half* __restrict__ B, const __half* __restrict__ B2, int b2row,
          const float* __restrict__ bias, float* __restrict__ C,
          __half* __restrict__ C16, int Ntot, int K)
{
    extern __shared__ char smem[];
    const uint32_t sb = smem_u32(smem);
    const int tid = threadIdx.x, wid = tid >> 5, lane = tid & 31;
    const int m0 = blockIdx.y * 128, n0 = blockIdx.x * 128;
    const int KT = K >> 5;
    const __half* Bp = (B2 != nullptr && m0 >= b2row) ? B2 : B;

    const int wm = (wid & 3) * 32;       // 4 warps in M
    const int wn = (wid >> 2) * 64;      // 2 warps in N
    const int g = lane >> 3, r = lane & 7;

    const uint32_t aRow = (uint32_t)(wm + (g & 1) * 8 + r);
    const uint32_t aCk  = (uint32_t)(g >> 1);
    const uint32_t bRow = (uint32_t)(wn + (g >> 1) * 8 + r);
    const uint32_t bCk  = (uint32_t)(g & 1);

    float acc[2][8][4];
#pragma unroll
    for (int i = 0; i < 2; i++)
#pragma unroll
        for (int j = 0; j < 8; j++)
#pragma unroll
            for (int q = 0; q < 4; q++) acc[i][j][q] = 0.0f;

    // 1024 16B chunks/stage (A 512, B 512) -> 4 per thread
    auto load_tile = [&](int kt, int s) {
        const int k0 = kt << 5;
        const uint32_t sbase = sb + (uint32_t)s * H_STAGE_BYTES;
#pragma unroll
        for (int q = 0; q < 4; q++) {
            int c = tid + q * 256;
            const __half* src;
            uint32_t dst;
            if (c < 512) {
                int rr = c >> 2, ck = c & 3;
                src = A + (size_t)(m0 + rr) * K + k0 + ck * 8;
                dst = sbase + H_A_OFF + (uint32_t)rr * ROWB + (uint32_t)ck * 16u;
            } else {
                int cc = c - 512;
                int rr = cc >> 2, ck = cc & 3;
                src = Bp + (size_t)(n0 + rr) * K + k0 + ck * 8;
                dst = sbase + H_B_OFF + (uint32_t)rr * ROWB + (uint32_t)ck * 16u;
            }
            cp16(dst, src);
        }
    };

    load_tile(0, 0); CP_COMMIT();
    load_tile(1, 1); CP_COMMIT();
    load_tile(2, 2); CP_COMMIT();

    for (int kt = 0; kt < KT; kt++) {
        CP_WAIT2();
        __syncthreads();
        if (kt + 3 < KT) load_tile(kt + 3, (kt + 3) % HSTAGE);
        CP_COMMIT();

        const uint32_t sbase = sb + (uint32_t)(kt % HSTAGE) * H_STAGE_BYTES;
#pragma unroll
        for (int kc = 0; kc < 2; kc++) {
            uint32_t af[2][4], bf[4][4];
            const uint32_t kofs = (uint32_t)(kc * 2) * 16u;
#pragma unroll
            for (int mi = 0; mi < 2; mi++)
                LDSM_X4(af[mi], sbase + H_A_OFF + (aRow + mi * 16) * ROWB + kofs + aCk * 16u);
#pragma unroll
            for (int bj = 0; bj < 4; bj++)
                LDSM_X4(bf[bj], sbase + H_B_OFF + (bRow + bj * 16) * ROWB + kofs + bCk * 16u);
#pragma unroll
            for (int mi = 0; mi < 2; mi++)
#pragma unroll
                for (int nj = 0; nj < 8; nj++)
                    MMA_FP16(acc[mi][nj], af[mi],
                             bf[nj >> 1][(nj & 1) * 2], bf[nj >> 1][(nj & 1) * 2 + 1]);
        }
    }

    const int rb = lane >> 2, cb = (lane & 3) * 2;
#pragma unroll
    for (int mi = 0; mi < 2; mi++) {
#pragma unroll
        for (int nj = 0; nj < 8; nj++) {
            int row0 = m0 + wm + mi * 16 + rb;
            int col = n0 + wn + nj * 8 + cb;
            float b0 = bias ? bias[col] : 0.0f;
            float b1 = bias ? bias[col + 1] : 0.0f;
            float v0 = acc[mi][nj][0] + b0, v1 = acc[mi][nj][1] + b1;
            float v2 = acc[mi][nj][2] + b0, v3 = acc[mi][nj][3] + b1;
            if (OUT16) {
                *(__half2*)(C16 + (size_t)row0 * Ntot + col) =
                    __halves2half2(__float2half_rn(v0), __float2half_rn(v1));
                *(__half2*)(C16 + (size_t)(row0 + 8) * Ntot + col) =
                    __halves2half2(__float2half_rn(v2), __float2half_rn(v3));
            } else {
                *(float2*)(C + (size_t)row0 * Ntot + col) = make_float2(v0, v1);
                *(float2*)(C + (size_t)(row0 + 8) * Ntot + col) = make_float2(v2, v3);
            }
        }
    }
}

// ---------------- merged prep: converts + transposes + fused bias ------------
// Conversion phase: 4x float4 per thread (64B) for MLP=4.
#define N4_X  (NTOK * DMODEL / 4)            // 8388608
#define N4_IW (NQKV * DMODEL / 4)            // 786432
#define N4_OW (DMODEL * DMODEL / 4)          // 262144
#define N4_ALL (N4_X + N4_IW + N4_OW)        // 9437184
#define CONV_BLOCKS (N4_ALL / 1024)          // 9216 (exact: 256 thr x 4 f4)
#define TRANS_BLOCKS 2048                    // 32*32*2
#define BIAS_BLOCKS 384
#define PREP_BLOCKS (CONV_BLOCKS + TRANS_BLOCKS + BIAS_BLOCKS)

__device__ __forceinline__ void conv_one(int j, const float* __restrict__ x,
                                         const float* __restrict__ iw,
                                         const float* __restrict__ ow)
{
    const float* in;
    __half* out;
    if (j < N4_X) { in = x; out = g_x16; }
    else if (j < N4_X + N4_IW) { j -= N4_X; in = iw; out = g_iw16; }
    else { j -= N4_X + N4_IW; in = ow; out = g_ow16; }
    float4 v = ((const float4*)in)[j];
    ((__half2*)out)[2 * j + 0] = __halves2half2(__float2half_rn(v.x), __float2half_rn(v.y));
    ((__half2*)out)[2 * j + 1] = __halves2half2(__float2half_rn(v.z), __float2half_rn(v.w));
}

__global__ void prep_kernel(const float* __restrict__ x,
                            const float* __restrict__ iw,
                            const float* __restrict__ ow,
                            const float* __restrict__ qk_w,
                            const float* __restrict__ v_w,
                            const float* __restrict__ in_b,
                            const float* __restrict__ bqk,
                            const float* __restrict__ bv)
{
    __shared__ float t[32][33];
    const int b = blockIdx.x, tid = threadIdx.x;

    if (b < CONV_BLOCKS) {
        // fp32 -> fp16 converts: x | in_w | out_w ; 4 float4 per thread
        int j0 = b * 1024 + tid;
#pragma unroll
        for (int q = 0; q < 4; q++)
            conv_one(j0 + q * 256, x, iw, ow);
    } else if (b < CONV_BLOCKS + TRANS_BLOCKS) {
        // transpose 1024x1024 fp32 -> fp16 (qk_w, v_w)
        int bb = b - CONV_BLOCKS;
        int z = bb >> 10, rem = bb & 1023;
        const float* W = z ? v_w : qk_w;
        __half* T = z ? g_vT16 : g_qkT16;
        int bx = (rem & 31) * 32, by = (rem >> 5) * 32;
        int tx = tid & 31, ty = tid >> 5;     // 32 x 8
        for (int j = ty; j < 32; j += 8)
            t[j][tx] = W[(size_t)(by + j) * DMODEL + bx + tx];
        __syncthreads();
        for (int j = ty; j < 32; j += 8)
            T[(size_t)(bx + j) * DMODEL + by + tx] = __float2half_rn(t[tx][j]);
    } else {
        // fused bias: CF = in_w @ (bqk|bv) + in_b
        int bb = b - CONV_BLOCKS - TRANS_BLOCKS;
        int gw = (bb * 256 + tid) >> 5;
        int lane = tid & 31;
        if (gw < NQKV) {
            const float* bvec = (gw < 2048) ? bqk : bv;
            const float* Arow = iw + (size_t)gw * DMODEL;
            float s = 0.0f;
            for (int j = lane; j < DMODEL; j += 32) s += Arow[j] * bvec[j];
#pragma unroll
            for (int off = 16; off; off >>= 1) s += __shfl_xor_sync(0xffffffffu, s, off);
            if (lane == 0) g_CF[gw] = s + in_b[gw];
        }
    }
}

// -------- segment attention (SEG=4, per head), 8B vector loads/stores --------
__global__ void attn_kernel()
{
    int gw   = (int)((blockIdx.x * blockDim.x + threadIdx.x) >> 5);
    int lane = threadIdx.x & 31;
    if (gw >= (NTOK / 4) * 8) return;
    int seg = gw >> 3, h = gw & 7, t0 = seg << 2;

    const __half* base = g_QKV16 + (size_t)t0 * NQKV + h * 128 + lane * 4;
    float4 q[4], k[4], v[4];
#pragma unroll
    for (int i = 0; i < 4; i++) {
        uint2 qr = *(const uint2*)(base + (size_t)i * NQKV);
        uint2 kr = *(const uint2*)(base + (size_t)i * NQKV + 1024);
        uint2 vr = *(const uint2*)(base + (size_t)i * NQKV + 2048);
        float2 q0 = __half22float2(*(const __half2*)&qr.x), q1 = __half22float2(*(const __half2*)&qr.y);
        float2 k0 = __half22float2(*(const __half2*)&kr.x), k1 = __half22float2(*(const __half2*)&kr.y);
        float2 v0 = __half22float2(*(const __half2*)&vr.x), v1 = __half22float2(*(const __half2*)&vr.y);
        q[i] = make_float4(q0.x, q0.y, q1.x, q1.y);
        k[i] = make_float4(k0.x, k0.y, k1.x, k1.y);
        v[i] = make_float4(v0.x, v0.y, v1.x, v1.y);
    }
    float s[4][4];
#pragma unroll
    for (int i = 0; i < 4; i++)
#pragma unroll
        for (int j = 0; j < 4; j++)
            s[i][j] = q[i].x * k[j].x + q[i].y * k[j].y + q[i].z * k[j].z + q[i].w * k[j].w;
#pragma unroll
    for (int off = 16; off; off >>= 1)
#pragma unroll
        for (int i = 0; i < 4; i++)
#pragma unroll
            for (int j = 0; j < 4; j++)
                s[i][j] += __shfl_xor_sync(0xffffffffu, s[i][j], off);

    const float scale = 0.08838834764831845f;
    float p[4][4];
#pragma unroll
    for (int i = 0; i < 4; i++) {
        float m = -1e30f;
#pragma unroll
        for (int j = 0; j < 4; j++) {
            float sv = (j == i) ? -1e30f : s[i][j] * scale;
            p[i][j] = sv; m = fmaxf(m, sv);
        }
        float sum = 0.0f;
#pragma unroll
        for (int j = 0; j < 4; j++) { p[i][j] = expf(p[i][j] - m); sum += p[i][j]; }
        float inv = 1.0f / sum;
#pragma unroll
        for (int j = 0; j < 4; j++) p[i][j] *= inv;
    }
    __half* ob = g_O16 + (size_t)t0 * DMODEL + h * 128 + lane * 4;
#pragma unroll
    for (int i = 0; i < 4; i++) {
        float o0 = p[i][0]*v[0].x + p[i][1]*v[1].x + p[i][2]*v[2].x + p[i][3]*v[3].x;
        float o1 = p[i][0]*v[0].y + p[i][1]*v[1].y + p[i][2]*v[2].y + p[i][3]*v[3].y;
        float o2 = p[i][0]*v[0].z + p[i][1]*v[1].z + p[i][2]*v[2].z + p[i][3]*v[3].z;
        float o3 = p[i][0]*v[0].w + p[i][1]*v[1].w + p[i][2]*v[2].w + p[i][3]*v[3].w;
        uint2 ov;
        __half2 h01 = __halves2half2(__float2half_rn(o0), __float2half_rn(o1));
        __half2 h23 = __halves2half2(__float2half_rn(o2), __float2half_rn(o3));
        ov.x = *(const uint32_t*)&h01;
        ov.y = *(const uint32_t*)&h23;
        *(uint2*)(ob + (size_t)i * DMODEL) = ov;
    }
}

// ----------------------------------------------------------------------------
extern "C" void kernel_launch(void* const* d_in, const int* in_sizes, int n_in,
                              void* d_out, int out_size)
{
    const float* x     = (const float*)d_in[0];
    const float* qk_w  = (const float*)d_in[1];
    const float* qk_b  = (const float*)d_in[2];
    const float* v_w   = (const float*)d_in[3];
    const float* v_b   = (const float*)d_in[4];
    const float* in_w  = (const float*)d_in[5];
    const float* in_b  = (const float*)d_in[6];
    const float* out_w = (const float*)d_in[7];
    const float* out_b = (const float*)d_in[8];
    float* out = (float*)d_out;
    (void)in_sizes; (void)n_in; (void)out_size;

    float *CF;
    __half *QKV16, *x16, *WF16, *O16, *ow16, *iw16, *qkT16, *vT16;
    cudaGetSymbolAddress((void**)&CF, g_CF);
    cudaGetSymbolAddress((void**)&QKV16, g_QKV16);
    cudaGetSymbolAddress((void**)&x16, g_x16);
    cudaGetSymbolAddress((void**)&WF16, g_WF16);
    cudaGetSymbolAddress((void**)&O16, g_O16);
    cudaGetSymbolAddress((void**)&ow16, g_ow16);
    cudaGetSymbolAddress((void**)&iw16, g_iw16);
    cudaGetSymbolAddress((void**)&qkT16, g_qkT16);
    cudaGetSymbolAddress((void**)&vT16, g_vT16);

    static bool attr_set = false;
    if (!attr_set) {
        cudaFuncSetAttribute(gemm_fp16<true>,  cudaFuncAttributeMaxDynamicSharedMemorySize, H_SMEM_TOTAL);
        cudaFuncSetAttribute(gemm_fp16<false>, cudaFuncAttributeMaxDynamicSharedMemorySize, H_SMEM_TOTAL);
        attr_set = true;
    }

    // 0) merged prep: converts + transposes + fused bias
    prep_kernel<<<PREP_BLOCKS, 256>>>(x, in_w, out_w, qk_w, v_w, in_b, qk_b, v_b);
    // 1) weight fusion (rows >= 2048 use vT16)
    gemm_fp16<true><<<dim3(DMODEL / 128, NQKV / 128), 256, H_SMEM_TOTAL>>>(
        iw16, qkT16, vT16, 2048, nullptr, nullptr, WF16, DMODEL, DMODEL);
    // 2) QKV = X @ WF^T + CF  [32768, 3072], fp16 in/out
    gemm_fp16<true><<<dim3(NQKV / 128, NTOK / 128), 256, H_SMEM_TOTAL>>>(
        x16, WF16, nullptr, 0, CF, nullptr, QKV16, NQKV, DMODEL);
    // 3) segment attention (fp16 -> fp16)
    attn_kernel<<<16384, 128>>>();
    // 4) out = O @ out_w^T + out_b  [32768, 1024], fp16 -> fp32
    gemm_fp16<false><<<dim3(DMODEL / 128, NTOK / 128), 256, H_SMEM_TOTAL>>>(
        O16, ow16, nullptr, 0, out_b, out, nullptr, DMODEL, DMODEL);
}

// round 14
// speedup vs baseline: 1.2791x; 1.1176x over previous
#include <cuda_runtime.h>
#include <cuda_fp16.h>
#include <cstdint>
#include <math.h>

// B=8, S=4096, D=1024, H=8, SEG=4, head_dim=128.
// Padding dead; segment shuffle is a permutation -> segments = consecutive
// 4-token groups. Weights fused: WF = in_proj @ (Wqk|Wqk|Wv), CF = in_proj@b + b.
// All GEMMs single-pass fp16 mma.sync, fp32 accum (measured rel_err 5.49e-4).
// R14: crossbar model -- warp 32x64 costs 192 B smem-read per MMA, capping at
// ~413 TF/s (measured 420). Warp 64x64 costs 128 B/MMA = crossbar-even with
// the HMMA pipe. New shape: CTA 128x128, 128 thr (4 warps, 2Mx2N, warp 64x64),
// 4 stages, 2 CTAs/SM. Prep/attn unchanged from R13.

#define DMODEL 1024
#define NTOK   32768
#define NQKV   3072

#define HSTAGE 4
#define ROWB   80u
#define A_ROWS 128u
#define B_ROWS 128u
#define H_A_OFF 0u
#define H_B_OFF (A_ROWS * ROWB)                     // 10240
#define H_STAGE_BYTES ((A_ROWS + B_ROWS) * ROWB)    // 20480
#define H_SMEM_TOTAL (HSTAGE * H_STAGE_BYTES)       // 81920 -> 2 CTAs/SM

// ------------------------- device scratch (no allocs) -----------------------
__device__ __align__(256) float   g_CF[NQKV];
__device__ __align__(256) __half  g_QKV16[(size_t)NTOK * NQKV];
__device__ __align__(256) __half  g_x16[(size_t)NTOK * DMODEL];
__device__ __align__(256) __half  g_WF16[(size_t)NQKV * DMODEL];
__device__ __align__(256) __half  g_O16[(size_t)NTOK * DMODEL];
__device__ __align__(256) __half  g_ow16[(size_t)DMODEL * DMODEL];
__device__ __align__(256) __half  g_iw16[(size_t)NQKV * DMODEL];
__device__ __align__(256) __half  g_qkT16[(size_t)DMODEL * DMODEL];
__device__ __align__(256) __half  g_vT16[(size_t)DMODEL * DMODEL];

// ------------------------------ helpers -------------------------------------
__device__ __forceinline__ uint32_t smem_u32(const void* p) {
    uint32_t a;
    asm("{ .reg .u64 t; cvta.to.shared.u64 t, %1; cvt.u32.u64 %0, t; }" : "=r"(a) : "l"(p));
    return a;
}
__device__ __forceinline__ void cp16(uint32_t dst, const void* src) {
    asm volatile("cp.async.cg.shared.global [%0], [%1], 16;" :: "r"(dst), "l"(src) : "memory");
}
#define CP_COMMIT() asm volatile("cp.async.commit_group;" ::: "memory")
#define CP_WAIT2()  asm volatile("cp.async.wait_group 2;" ::: "memory")

#define LDSM_X4(R, a) \
    asm volatile("ldmatrix.sync.aligned.m8n8.x4.shared.b16 {%0,%1,%2,%3}, [%4];" \
        : "=r"((R)[0]), "=r"((R)[1]), "=r"((R)[2]), "=r"((R)[3]) : "r"(a))

#define MMA_FP16(d, a, b0, b1) \
    asm volatile("mma.sync.aligned.m16n8k16.row.col.f32.f16.f16.f32 " \
        "{%0,%1,%2,%3}, {%4,%5,%6,%7}, {%8,%9}, {%0,%1,%2,%3};" \
        : "+f"((d)[0]), "+f"((d)[1]), "+f"((d)[2]), "+f"((d)[3]) \
        : "r"((a)[0]), "r"((a)[1]), "r"((a)[2]), "r"((a)[3]), "r"(b0), "r"(b1))

// ----------------------------------------------------------------------------
// Single-pass fp16 GEMM: C[M,Ntot] = A@B^T (+bias).
// A: [M,K] fp16 K-major; B: [Ntot,K] fp16 K-major.
// B2 != null: row blocks with m0 >= b2row use B2 instead of B (fusion merge).
// CTA 128x128, BK=32, 128 threads (4 warps, 2Mx2N, warp 64x64 -> 128 B
// smem-read per MMA, crossbar-even), 4 stages, 2 CTAs/SM.
// OUT16=true -> fp16 C16; false -> fp32 C.
// ----------------------------------------------------------------------------
template <bool OUT16>
__global__ void __launch_bounds__(128, 2)
gemm_fp16(const __half* __restrict__ A,
          const __half* __restrict__ B, const __half* __restrict__ B2, int b2row,
          const float* __restrict__ bias, float* __restrict__ C,
          __half* __restrict__ C16, int Ntot, int K)
{
    extern __shared__ char smem[];
    const uint32_t sb = smem_u32(smem);
    const int tid = threadIdx.x, wid = tid >> 5, lane = tid & 31;
    const int m0 = blockIdx.y * 128, n0 = blockIdx.x * 128;
    const int KT = K >> 5;
    const __half* Bp = (B2 != nullptr && m0 >= b2row) ? B2 : B;

    const int wm = (wid & 1) * 64;       // 2 warps in M
    const int wn = (wid >> 1) * 64;      // 2 warps in N
    const int g = lane >> 3, r = lane & 7;

    const uint32_t aRow = (uint32_t)(wm + (g & 1) * 8 + r);
    const uint32_t aCk  = (uint32_t)(g >> 1);
    const uint32_t bRow = (uint32_t)(wn + (g >> 1) * 8 + r);
    const uint32_t bCk  = (uint32_t)(g & 1);

    float acc[4][8][4];
#pragma unroll
    for (int i = 0; i < 4; i++)
#pragma unroll
        for (int j = 0; j < 8; j++)
#pragma unroll
            for (int q = 0; q < 4; q++) acc[i][j][q] = 0.0f;

    // 1024 16B chunks/stage (A 512, B 512) -> 8 per thread at 128 threads
    auto load_tile = [&](int kt, int s) {
        const int k0 = kt << 5;
        const uint32_t sbase = sb + (uint32_t)s * H_STAGE_BYTES;
#pragma unroll
        for (int q = 0; q < 8; q++) {
            int c = tid + q * 128;
            const __half* src;
            uint32_t dst;
            if (c < 512) {
                int rr = c >> 2, ck = c & 3;
                src = A + (size_t)(m0 + rr) * K + k0 + ck * 8;
                dst = sbase + H_A_OFF + (uint32_t)rr * ROWB + (uint32_t)ck * 16u;
            } else {
                int cc = c - 512;
                int rr = cc >> 2, ck = cc & 3;
                src = Bp + (size_t)(n0 + rr) * K + k0 + ck * 8;
                dst = sbase + H_B_OFF + (uint32_t)rr * ROWB + (uint32_t)ck * 16u;
            }
            cp16(dst, src);
        }
    };

    load_tile(0, 0); CP_COMMIT();
    load_tile(1, 1); CP_COMMIT();
    load_tile(2, 2); CP_COMMIT();

    for (int kt = 0; kt < KT; kt++) {
        CP_WAIT2();
        __syncthreads();
        if (kt + 3 < KT) load_tile(kt + 3, (kt + 3) % HSTAGE);
        CP_COMMIT();

        const uint32_t sbase = sb + (uint32_t)(kt % HSTAGE) * H_STAGE_BYTES;
#pragma unroll
        for (int kc = 0; kc < 2; kc++) {
            uint32_t af[4][4], bf[4][4];
            const uint32_t kofs = (uint32_t)(kc * 2) * 16u;
#pragma unroll
            for (int mi = 0; mi < 4; mi++)
                LDSM_X4(af[mi], sbase + H_A_OFF + (aRow + mi * 16) * ROWB + kofs + aCk * 16u);
#pragma unroll
            for (int bj = 0; bj < 4; bj++)
                LDSM_X4(bf[bj], sbase + H_B_OFF + (bRow + bj * 16) * ROWB + kofs + bCk * 16u);
#pragma unroll
            for (int mi = 0; mi < 4; mi++)
#pragma unroll
                for (int nj = 0; nj < 8; nj++)
                    MMA_FP16(acc[mi][nj], af[mi],
                             bf[nj >> 1][(nj & 1) * 2], bf[nj >> 1][(nj & 1) * 2 + 1]);
        }
    }

    const int rb = lane >> 2, cb = (lane & 3) * 2;
#pragma unroll
    for (int mi = 0; mi < 4; mi++) {
#pragma unroll
        for (int nj = 0; nj < 8; nj++) {
            int row0 = m0 + wm + mi * 16 + rb;
            int col = n0 + wn + nj * 8 + cb;
            float b0 = bias ? bias[col] : 0.0f;
            float b1 = bias ? bias[col + 1] : 0.0f;
            float v0 = acc[mi][nj][0] + b0, v1 = acc[mi][nj][1] + b1;
            float v2 = acc[mi][nj][2] + b0, v3 = acc[mi][nj][3] + b1;
            if (OUT16) {
                *(__half2*)(C16 + (size_t)row0 * Ntot + col) =
                    __halves2half2(__float2half_rn(v0), __float2half_rn(v1));
                *(__half2*)(C16 + (size_t)(row0 + 8) * Ntot + col) =
                    __halves2half2(__float2half_rn(v2), __float2half_rn(v3));
            } else {
                *(float2*)(C + (size_t)row0 * Ntot + col) = make_float2(v0, v1);
                *(float2*)(C + (size_t)(row0 + 8) * Ntot + col) = make_float2(v2, v3);
            }
        }
    }
}

// ---------------- merged prep: converts + transposes + fused bias ------------
#define N4_X  (NTOK * DMODEL / 4)            // 8388608
#define N4_IW (NQKV * DMODEL / 4)            // 786432
#define N4_OW (DMODEL * DMODEL / 4)          // 262144
#define N4_ALL (N4_X + N4_IW + N4_OW)        // 9437184
#define CONV_BLOCKS (N4_ALL / 1024)          // 9216 (exact: 256 thr x 4 f4)
#define TRANS_BLOCKS 2048                    // 32*32*2
#define BIAS_BLOCKS 384
#define PREP_BLOCKS (CONV_BLOCKS + TRANS_BLOCKS + BIAS_BLOCKS)

__device__ __forceinline__ void conv_one(int j, const float* __restrict__ x,
                                         const float* __restrict__ iw,
                                         const float* __restrict__ ow)
{
    const float* in;
    __half* out;
    if (j < N4_X) { in = x; out = g_x16; }
    else if (j < N4_X + N4_IW) { j -= N4_X; in = iw; out = g_iw16; }
    else { j -= N4_X + N4_IW; in = ow; out = g_ow16; }
    float4 v = ((const float4*)in)[j];
    ((__half2*)out)[2 * j + 0] = __halves2half2(__float2half_rn(v.x), __float2half_rn(v.y));
    ((__half2*)out)[2 * j + 1] = __halves2half2(__float2half_rn(v.z), __float2half_rn(v.w));
}

__global__ void prep_kernel(const float* __restrict__ x,
                            const float* __restrict__ iw,
                            const float* __restrict__ ow,
                            const float* __restrict__ qk_w,
                            const float* __restrict__ v_w,
                            const float* __restrict__ in_b,
                            const float* __restrict__ bqk,
                            const float* __restrict__ bv)
{
    __shared__ float t[32][33];
    const int b = blockIdx.x, tid = threadIdx.x;

    if (b < CONV_BLOCKS) {
        int j0 = b * 1024 + tid;
#pragma unroll
        for (int q = 0; q < 4; q++)
            conv_one(j0 + q * 256, x, iw, ow);
    } else if (b < CONV_BLOCKS + TRANS_BLOCKS) {
        int bb = b - CONV_BLOCKS;
        int z = bb >> 10, rem = bb & 1023;
        const float* W = z ? v_w : qk_w;
        __half* T = z ? g_vT16 : g_qkT16;
        int bx = (rem & 31) * 32, by = (rem >> 5) * 32;
        int tx = tid & 31, ty = tid >> 5;     // 32 x 8
        for (int j = ty; j < 32; j += 8)
            t[j][tx] = W[(size_t)(by + j) * DMODEL + bx + tx];
        __syncthreads();
        for (int j = ty; j < 32; j += 8)
            T[(size_t)(bx + j) * DMODEL + by + tx] = __float2half_rn(t[tx][j]);
    } else {
        int bb = b - CONV_BLOCKS - TRANS_BLOCKS;
        int gw = (bb * 256 + tid) >> 5;
        int lane = tid & 31;
        if (gw < NQKV) {
            const float* bvec = (gw < 2048) ? bqk : bv;
            const float* Arow = iw + (size_t)gw * DMODEL;
            float s = 0.0f;
            for (int j = lane; j < DMODEL; j += 32) s += Arow[j] * bvec[j];
#pragma unroll
            for (int off = 16; off; off >>= 1) s += __shfl_xor_sync(0xffffffffu, s, off);
            if (lane == 0) g_CF[gw] = s + in_b[gw];
        }
    }
}

// -------- segment attention (SEG=4, per head), 8B vector loads/stores --------
__global__ void attn_kernel()
{
    int gw   = (int)((blockIdx.x * blockDim.x + threadIdx.x) >> 5);
    int lane = threadIdx.x & 31;
    if (gw >= (NTOK / 4) * 8) return;
    int seg = gw >> 3, h = gw & 7, t0 = seg << 2;

    const __half* base = g_QKV16 + (size_t)t0 * NQKV + h * 128 + lane * 4;
    float4 q[4], k[4], v[4];
#pragma unroll
    for (int i = 0; i < 4; i++) {
        uint2 qr = *(const uint2*)(base + (size_t)i * NQKV);
        uint2 kr = *(const uint2*)(base + (size_t)i * NQKV + 1024);
        uint2 vr = *(const uint2*)(base + (size_t)i * NQKV + 2048);
        float2 q0 = __half22float2(*(const __half2*)&qr.x), q1 = __half22float2(*(const __half2*)&qr.y);
        float2 k0 = __half22float2(*(const __half2*)&kr.x), k1 = __half22float2(*(const __half2*)&kr.y);
        float2 v0 = __half22float2(*(const __half2*)&vr.x), v1 = __half22float2(*(const __half2*)&vr.y);
        q[i] = make_float4(q0.x, q0.y, q1.x, q1.y);
        k[i] = make_float4(k0.x, k0.y, k1.x, k1.y);
        v[i] = make_float4(v0.x, v0.y, v1.x, v1.y);
    }
    float s[4][4];
#pragma unroll
    for (int i = 0; i < 4; i++)
#pragma unroll
        for (int j = 0; j < 4; j++)
            s[i][j] = q[i].x * k[j].x + q[i].y * k[j].y + q[i].z * k[j].z + q[i].w * k[j].w;
#pragma unroll
    for (int off = 16; off; off >>= 1)
#pragma unroll
        for (int i = 0; i < 4; i++)
#pragma unroll
            for (int j = 0; j < 4; j++)
                s[i][j] += __shfl_xor_sync(0xffffffffu, s[i][j], off);

    const float scale = 0.08838834764831845f;
    float p[4][4];
#pragma unroll
    for (int i = 0; i < 4; i++) {
        float m = -1e30f;
#pragma unroll
        for (int j = 0; j < 4; j++) {
            float sv = (j == i) ? -1e30f : s[i][j] * scale;
            p[i][j] = sv; m = fmaxf(m, sv);
        }
        float sum = 0.0f;
#pragma unroll
        for (int j = 0; j < 4; j++) { p[i][j] = expf(p[i][j] - m); sum += p[i][j]; }
        float inv = 1.0f / sum;
#pragma unroll
        for (int j = 0; j < 4; j++) p[i][j] *= inv;
    }
    __half* ob = g_O16 + (size_t)t0 * DMODEL + h * 128 + lane * 4;
#pragma unroll
    for (int i = 0; i < 4; i++) {
        float o0 = p[i][0]*v[0].x + p[i][1]*v[1].x + p[i][2]*v[2].x + p[i][3]*v[3].x;
        float o1 = p[i][0]*v[0].y + p[i][1]*v[1].y + p[i][2]*v[2].y + p[i][3]*v[3].y;
        float o2 = p[i][0]*v[0].z + p[i][1]*v[1].z + p[i][2]*v[2].z + p[i][3]*v[3].z;
        float o3 = p[i][0]*v[0].w + p[i][1]*v[1].w + p[i][2]*v[2].w + p[i][3]*v[3].w;
        uint2 ov;
        __half2 h01 = __halves2half2(__float2half_rn(o0), __float2half_rn(o1));
        __half2 h23 = __halves2half2(__float2half_rn(o2), __float2half_rn(o3));
        ov.x = *(const uint32_t*)&h01;
        ov.y = *(const uint32_t*)&h23;
        *(uint2*)(ob + (size_t)i * DMODEL) = ov;
    }
}

// ----------------------------------------------------------------------------
extern "C" void kernel_launch(void* const* d_in, const int* in_sizes, int n_in,
                              void* d_out, int out_size)
{
    const float* x     = (const float*)d_in[0];
    const float* qk_w  = (const float*)d_in[1];
    const float* qk_b  = (const float*)d_in[2];
    const float* v_w   = (const float*)d_in[3];
    const float* v_b   = (const float*)d_in[4];
    const float* in_w  = (const float*)d_in[5];
    const float* in_b  = (const float*)d_in[6];
    const float* out_w = (const float*)d_in[7];
    const float* out_b = (const float*)d_in[8];
    float* out = (float*)d_out;
    (void)in_sizes; (void)n_in; (void)out_size;

    float *CF;
    __half *QKV16, *x16, *WF16, *O16, *ow16, *iw16, *qkT16, *vT16;
    cudaGetSymbolAddress((void**)&CF, g_CF);
    cudaGetSymbolAddress((void**)&QKV16, g_QKV16);
    cudaGetSymbolAddress((void**)&x16, g_x16);
    cudaGetSymbolAddress((void**)&WF16, g_WF16);
    cudaGetSymbolAddress((void**)&O16, g_O16);
    cudaGetSymbolAddress((void**)&ow16, g_ow16);
    cudaGetSymbolAddress((void**)&iw16, g_iw16);
    cudaGetSymbolAddress((void**)&qkT16, g_qkT16);
    cudaGetSymbolAddress((void**)&vT16, g_vT16);

    static bool attr_set = false;
    if (!attr_set) {
        cudaFuncSetAttribute(gemm_fp16<true>,  cudaFuncAttributeMaxDynamicSharedMemorySize, H_SMEM_TOTAL);
        cudaFuncSetAttribute(gemm_fp16<false>, cudaFuncAttributeMaxDynamicSharedMemorySize, H_SMEM_TOTAL);
        attr_set = true;
    }

    // 0) merged prep: converts + transposes + fused bias
    prep_kernel<<<PREP_BLOCKS, 256>>>(x, in_w, out_w, qk_w, v_w, in_b, qk_b, v_b);
    // 1) weight fusion (rows >= 2048 use vT16)
    gemm_fp16<true><<<dim3(DMODEL / 128, NQKV / 128), 128, H_SMEM_TOTAL>>>(
        iw16, qkT16, vT16, 2048, nullptr, nullptr, WF16, DMODEL, DMODEL);
    // 2) QKV = X @ WF^T + CF  [32768, 3072], fp16 in/out
    gemm_fp16<true><<<dim3(NQKV / 128, NTOK / 128), 128, H_SMEM_TOTAL>>>(
        x16, WF16, nullptr, 0, CF, nullptr, QKV16, NQKV, DMODEL);
    // 3) segment attention (fp16 -> fp16)
    attn_kernel<<<16384, 128>>>();
    // 4) out = O @ out_w^T + out_b  [32768, 1024], fp16 -> fp32
    gemm_fp16<false><<<dim3(DMODEL / 128, NTOK / 128), 128, H_SMEM_TOTAL>>>(
        O16, ow16, nullptr, 0, out_b, out, nullptr, DMODEL, DMODEL);
}